// round 9
// baseline (speedup 1.0000x reference)
#include <cuda_runtime.h>
#include <cstdint>

#define BB 8
#define CC 256
#define HH 160
#define WW 160
#define HW (HH*WW)          // 25600

// edge kernel geometry: 32-col ALIGNED x 8-row tile; 8 warps split 256 channels
#define ETW 32
#define ETH 8
#define NXT 5               // 5*32 = 160, exact
#define NYT 20              // 20*8 = 160, exact
#define CPW 32              // channels per warp

// ---- scratch (no allocations allowed) ----
__device__ float g_c_sum[BB*CC];      // per-(b,c) sum of g
__device__ float g_w_gate[BB*CC];     // channel gate
__device__ float g_sum_x[BB*HW];      // per-pixel sum over channels of x
__device__ float g_sum_g[BB*HW];      // per-pixel sum over channels of g
__device__ float g_max_x[BB*HW];      // per-pixel max of x
__device__ float g_max_g[BB*HW];      // per-pixel max of g
__device__ float g_s_map[BB*HW];      // spatial gate
__device__ float g_ab[2];             // softplus(alpha), softplus(beta)

__device__ __forceinline__ float sqrt_approx(float v) {
    float r;
    asm("sqrt.approx.f32 %0, %1;" : "=f"(r) : "f"(v));
    return r;
}

__global__ void zero_kernel() {
    int i = blockIdx.x * 256 + threadIdx.x;
    if (i < BB*CC) g_c_sum[i] = 0.f;
}

// horizontal Sobel stage for one row of one channel stream
#define HROW(PTR, ROK, HD, HS, VOUT)                                   \
    {                                                                  \
        float v_ = (ROK) ? (PTR)[0] : 0.f;                             \
        float e_ = ((ROK) && eact) ? (PTR)[eoff] : 0.f;                \
        float xl_ = __shfl_up_sync(0xffffffffu, v_, 1);                \
        if (lane == 0)  xl_ = e_;                                      \
        float xr_ = __shfl_down_sync(0xffffffffu, v_, 1);              \
        if (lane == 31) xr_ = e_;                                      \
        HD = xl_ - xr_;                                                \
        HS = fmaf(2.f, v_, xl_) + xr_;                                 \
        VOUT = v_;                                                     \
    }

// ---------------------------------------------------------------------------
// Kernel 1: Sobel magnitude + all reductions.
// Aligned 32-col tiles (lane == column), 2-channel-interleaved inner loop
// for ILP, 3-row register window, shfl horizontal stage, no smem/barriers
// in the channel loop. 8 warps x 32 channels on the same 32x8 strip;
// two-phase cross-warp combine (16.6 KB smem); plain global stores.
// grid (5, 20, 8), block 256.
// ---------------------------------------------------------------------------
__global__ __launch_bounds__(256) void k_edge(const float* __restrict__ x) {
    __shared__ float buf[8*2*260];          // [warp][stat][px(pad 260)]

    const int tid  = threadIdx.x;
    const int lane = tid & 31;
    const int wid  = tid >> 5;
    const int tx0  = blockIdx.x * ETW;
    const int ry0  = blockIdx.y * ETH;
    const int b    = blockIdx.z;

    const int col = tx0 + lane;             // always < WW
    const bool eact = ((lane == 0) && (col > 0)) ||
                      ((lane == 31) && (col + 1 < WW));
    const int  eoff = (lane == 0) ? -1 : 1;

    float sx[ETH], sg[ETH], mx[ETH], mg[ETH];
    #pragma unroll
    for (int k = 0; k < ETH; k++) {
        sx[k] = 0.f; sg[k] = 0.f; mx[k] = -3.4e38f; mg[k] = 0.f;
    }

    const bool rm1ok = (ry0 > 0);
    const bool rp8ok = (ry0 + ETH < HH);

    const float* xb = x + ((size_t)b * CC + (size_t)wid * CPW) * HW + col;

    for (int ch = 0; ch < CPW; ch += 2) {
        const float* xc0 = xb + (size_t)ch * HW;
        const float* xc1 = xc0 + HW;
        float cs0 = 0.f, cs1 = 0.f;

        float hdA0, hsA0, hdB0, hsB0, xp0, dmy0;
        float hdA1, hsA1, hdB1, hsB1, xp1, dmy1;
        HROW(xc0 + (size_t)(ry0-1)*WW, rm1ok, hdA0, hsA0, dmy0)
        HROW(xc1 + (size_t)(ry0-1)*WW, rm1ok, hdA1, hsA1, dmy1)
        HROW(xc0 + (size_t)ry0*WW,     true,  hdB0, hsB0, xp0)
        HROW(xc1 + (size_t)ry0*WW,     true,  hdB1, hsB1, xp1)
        (void)dmy0; (void)dmy1;

        #pragma unroll
        for (int k = 0; k < ETH; k++) {
            bool rok = (k < ETH-1) || rp8ok;      // row ry0+k+1
            float hdC0, hsC0, v0, hdC1, hsC1, v1;
            HROW(xc0 + (size_t)(ry0+k+1)*WW, rok, hdC0, hsC0, v0)
            HROW(xc1 + (size_t)(ry0+k+1)*WW, rok, hdC1, hsC1, v1)

            float gxa = fmaf(2.f, hdB0, hdA0) + hdC0;  // 4*true gx
            float gya = hsA0 - hsC0;                   // 4*true gy
            float g0  = 0.25f * sqrt_approx(fmaf(gya, gya, fmaf(gxa, gxa, 1.6e-11f)));
            float gxb = fmaf(2.f, hdB1, hdA1) + hdC1;
            float gyb = hsA1 - hsC1;
            float g1  = 0.25f * sqrt_approx(fmaf(gyb, gyb, fmaf(gxb, gxb, 1.6e-11f)));

            sx[k] += (xp0 + xp1);
            mx[k] = fmaxf(mx[k], fmaxf(xp0, xp1));
            sg[k] += (g0 + g1);
            mg[k] = fmaxf(mg[k], fmaxf(g0, g1));
            cs0 += g0;  cs1 += g1;

            hdA0 = hdB0; hdB0 = hdC0; hsA0 = hsB0; hsB0 = hsC0; xp0 = v0;
            hdA1 = hdB1; hdB1 = hdC1; hsA1 = hsB1; hsB1 = hsC1; xp1 = v1;
        }

        // two interleaved butterfly reductions
        #pragma unroll
        for (int off = 16; off; off >>= 1) {
            cs0 += __shfl_xor_sync(0xffffffffu, cs0, off);
            cs1 += __shfl_xor_sync(0xffffffffu, cs1, off);
        }
        if (lane == 0) {
            atomicAdd(&g_c_sum[b*CC + wid*CPW + ch],     cs0);
            atomicAdd(&g_c_sum[b*CC + wid*CPW + ch + 1], cs1);
        }
    }

    // two-phase cross-warp combine (sx,mx then sg,mg) — halves smem
    const int pbase = b * HW + ry0 * WW + tx0;
    {
        float* mybuf = buf + wid * (2*260);
        #pragma unroll
        for (int k = 0; k < ETH; k++) {
            int px = k * 32 + lane;
            mybuf[px]       = sx[k];
            mybuf[260 + px] = mx[k];
        }
    }
    __syncthreads();
    {
        float rs = buf[tid], rm = buf[260 + tid];
        #pragma unroll
        for (int w = 1; w < 8; w++) {
            rs += buf[w*520 + tid];
            rm = fmaxf(rm, buf[w*520 + 260 + tid]);
        }
        int p = pbase + (tid >> 5) * WW + (tid & 31);
        g_sum_x[p] = rs;
        g_max_x[p] = rm;
    }
    __syncthreads();
    {
        float* mybuf = buf + wid * (2*260);
        #pragma unroll
        for (int k = 0; k < ETH; k++) {
            int px = k * 32 + lane;
            mybuf[px]       = sg[k];
            mybuf[260 + px] = mg[k];
        }
    }
    __syncthreads();
    {
        float rs = buf[tid], rm = buf[260 + tid];
        #pragma unroll
        for (int w = 1; w < 8; w++) {
            rs += buf[w*520 + tid];
            rm = fmaxf(rm, buf[w*520 + 260 + tid]);
        }
        int p = pbase + (tid >> 5) * WW + (tid & 31);
        g_sum_g[p] = rs;
        g_max_g[p] = rm;
    }
}

// ---------------------------------------------------------------------------
// Kernel 2: fused gates. Blocks 0..799: spatial 7x7 conv (16x16 tiles).
// Blocks 800..807: channel MLP for batch (blk-800). block = 256.
// ---------------------------------------------------------------------------
#define STILE 16
#define SHALO 22
#define SHE (SHALO*SHALO)    // 484
__global__ __launch_bounds__(256) void k_gates(const float* __restrict__ w1,
                                               const float* __restrict__ w2,
                                               const float* __restrict__ sw,
                                               const float* __restrict__ sb,
                                               const float* __restrict__ alpha,
                                               const float* __restrict__ beta) {
    __shared__ float sm[4*SHE + 200];
    const int tid = threadIdx.x;
    const int blk = blockIdx.x;

    if (blk < 800) {
        const int bx = blk % 10, by = (blk / 10) % 10, b = blk / 100;
        const int tx0 = bx * STILE, ty0 = by * STILE;
        float* t   = sm;
        float* wsm = sm + 4*SHE;
        if (tid < 196) wsm[tid] = sw[tid];

        const int pbase = b * HW;
        const float invC = 1.f / CC;
        for (int i = tid; i < 4*SHE; i += 256) {
            int ch  = i / SHE;
            int rem = i - ch * SHE;
            int r   = rem / SHALO, cc2 = rem - r * SHALO;
            int gy  = ty0 - 3 + r, gx = tx0 - 3 + cc2;
            float v = 0.f;
            if ((unsigned)gy < HH && (unsigned)gx < WW) {
                int p = pbase + gy * WW + gx;
                if      (ch == 0) v = g_sum_x[p] * invC;
                else if (ch == 1) v = g_max_x[p];
                else if (ch == 2) v = g_sum_g[p] * invC;
                else              v = g_max_g[p];
            }
            t[i] = v;
        }
        __syncthreads();

        const int pr = tid >> 4, pc = tid & 15;
        float acc = sb[0];
        #pragma unroll
        for (int ch = 0; ch < 4; ch++) {
            #pragma unroll
            for (int u = 0; u < 7; u++) {
                const float* rp = &t[ch*SHE + (pr + u)*SHALO + pc];
                const float* wr = &wsm[ch*49 + u*7];
                #pragma unroll
                for (int v = 0; v < 7; v++) acc = fmaf(rp[v], wr[v], acc);
            }
        }
        g_s_map[pbase + (ty0 + pr)*WW + tx0 + pc] = 1.f / (1.f + __expf(-acc));
    } else {
        const int b = blk - 800;
        float* cv = sm;
        float* h  = sm + CC;
        cv[tid] = g_c_sum[b*CC + tid] * (1.f / HW);
        __syncthreads();
        if (tid < 16) {
            float acc = 0.f;
            for (int c2 = 0; c2 < CC; c2++) acc = fmaf(cv[c2], w1[tid*CC + c2], acc);
            h[tid] = fmaxf(acc, 0.f);
        }
        __syncthreads();
        float acc = 0.f;
        #pragma unroll
        for (int j = 0; j < 16; j++) acc = fmaf(h[j], w2[tid*16 + j], acc);
        g_w_gate[b*CC + tid] = 1.f / (1.f + __expf(-acc));
        if (b == 0 && tid == 0) {
            float av = alpha[0], bv = beta[0];
            g_ab[0] = (av > 20.f) ? av : log1pf(expf(av));
            g_ab[1] = (bv > 20.f) ? bv : log1pf(expf(bv));
        }
    }
}

// ---------------------------------------------------------------------------
// Kernel 3: streaming apply. out = x * (1 + a*s) * (1 + b*w). float4,
// streaming cache hints (no reuse of x or out).
// ---------------------------------------------------------------------------
__global__ __launch_bounds__(256) void k_apply(const float* __restrict__ x,
                                               float* __restrict__ out) {
    const float a  = g_ab[0];
    const float bb = g_ab[1];
    const int hw4  = HW / 4;             // 6400
    int i4 = blockIdx.x * 256 + threadIdx.x;
    int cl = i4 / hw4;                   // b*CC + c   (0..2047)
    int b  = cl >> 8;
    int p4 = i4 - cl * hw4;
    float wg = fmaf(bb, g_w_gate[cl], 1.f);
    float4 s4 = ((const float4*)g_s_map)[b*hw4 + p4];
    float4 x4 = __ldcs((const float4*)x + i4);
    float4 o;
    o.x = x4.x * fmaf(a, s4.x, 1.f) * wg;
    o.y = x4.y * fmaf(a, s4.y, 1.f) * wg;
    o.z = x4.z * fmaf(a, s4.z, 1.f) * wg;
    o.w = x4.w * fmaf(a, s4.w, 1.f) * wg;
    __stcs((float4*)out + i4, o);
}

// ---------------------------------------------------------------------------
extern "C" void kernel_launch(void* const* d_in, const int* in_sizes, int n_in,
                              void* d_out, int out_size) {
    const float* x  = (const float*)d_in[0];
    const float* w1 = (const float*)d_in[1];
    const float* w2 = (const float*)d_in[2];
    const float* sw = (const float*)d_in[3];
    const float* sb = (const float*)d_in[4];
    const float* al = (const float*)d_in[5];
    const float* be = (const float*)d_in[6];
    float* out = (float*)d_out;

    zero_kernel<<<(BB*CC + 255)/256, 256>>>();
    dim3 g1(NXT, NYT, BB);
    k_edge<<<g1, 256>>>(x);
    k_gates<<<808, 256>>>(w1, w2, sw, sb, al, be);
    int total4 = BB * CC * HW / 4;
    k_apply<<<(total4 + 255)/256, 256>>>(x, out);
}